// round 9
// baseline (speedup 1.0000x reference)
#include <cuda_runtime.h>
#include <cstdint>
#include <cstddef>

#define BB    64
#define TT    20
#define EMBD  512
#define VOC   32000
#define NSTEP 19
#define GDIM  2048
#define ETILE 4
#define NCTA  128

// ---------------- scratch (no allocations allowed) ----------------
__device__ float g_embsteps[NSTEP * BB * EMBD];   // raw fp32 (xpre GEMM input)
__device__ float g_seq[BB * TT * EMBD];           // tf32-ROUNDED values (proj input)
__device__ float g_xpre[NSTEP * BB * GDIM];       // [t][b][4E]
__device__ float g_c[BB * EMBD];
__device__ float g_h_hi[BB * EMBD];               // tf32 hi plane of h
__device__ float g_h_lo[BB * EMBD];               // tf32 lo plane of h
__device__ float g_whh_hi[GDIM * EMBD];           // W_hh hi/lo planes
__device__ float g_whh_lo[GDIM * EMBD];
__device__ float g_wout_r[VOC * EMBD];            // W_out tf32-rounded
__device__ unsigned g_bar;                        // grid barrier counter

// ---------------- helpers ----------------
__device__ __forceinline__ unsigned f2tf(float x) {
    unsigned u;
    asm("cvt.rna.tf32.f32 %0, %1;" : "=r"(u) : "f"(x));
    return u;
}
__device__ __forceinline__ float tfr(float x) { return __uint_as_float(f2tf(x)); }

__device__ __forceinline__ void mma8(float c[4], const unsigned a[4], const unsigned b[2]) {
    asm volatile(
        "mma.sync.aligned.m16n8k8.row.col.f32.tf32.tf32.f32 "
        "{%0,%1,%2,%3}, {%4,%5,%6,%7}, {%8,%9}, {%0,%1,%2,%3};"
        : "+f"(c[0]), "+f"(c[1]), "+f"(c[2]), "+f"(c[3])
        : "r"(a[0]), "r"(a[1]), "r"(a[2]), "r"(a[3]), "r"(b[0]), "r"(b[1]));
}

__device__ __forceinline__ float fsig(float x) { return 1.f / (1.f + __expf(-x)); }
__device__ __forceinline__ float ftanh(float x) {
    float e = __expf(-2.f * x);
    return (1.f - e) / (1.f + e);
}

// ---------------- init: embedding gather + h0/c0 + barrier reset ----------------
__global__ void init_kernel(const float* __restrict__ features,
                            const int*   __restrict__ captions,
                            const float* __restrict__ W_emb) {
    int idx = blockIdx.x * blockDim.x + threadIdx.x;       // over B*T*(E/4)
    if (idx == 0) g_bar = 0;
    if (idx >= BB * TT * (EMBD / 4)) return;
    int e4 = idx & (EMBD / 4 - 1);
    int bt = idx >> 7;
    int t = bt % TT, b = bt / TT;
    int cap = captions[b * TT + t];
    float4 v = *(const float4*)(W_emb + (size_t)cap * EMBD + e4 * 4);
    if (t < NSTEP)
        *(float4*)(g_embsteps + ((size_t)(t * BB + b)) * EMBD + e4 * 4) = v;
    if (t == 0) {
        float4 vr = make_float4(tfr(v.x), tfr(v.y), tfr(v.z), tfr(v.w));
        *(float4*)(g_seq + ((size_t)b * TT) * EMBD + e4 * 4) = vr;        // seq[:,0]
        float4 z = make_float4(0.f, 0.f, 0.f, 0.f);
        *(float4*)(g_h_hi + (size_t)b * EMBD + e4 * 4) = z;
        *(float4*)(g_h_lo + (size_t)b * EMBD + e4 * 4) = z;
        *(float4*)(g_c + (size_t)b * EMBD + e4 * 4) =
            *(const float4*)(features + (size_t)b * EMBD + e4 * 4);       // c0
    }
}

// ---------------- prep: split W_hh hi/lo; round W_out ----------------
__global__ void prep_whh(const float* __restrict__ W) {
    int i = blockIdx.x * blockDim.x + threadIdx.x;   // over GDIM*EMBD/4
    if (i >= GDIM * EMBD / 4) return;
    float4 w = ((const float4*)W)[i];
    float4 hi = make_float4(tfr(w.x), tfr(w.y), tfr(w.z), tfr(w.w));
    float4 lo = make_float4(tfr(w.x - hi.x), tfr(w.y - hi.y),
                            tfr(w.z - hi.z), tfr(w.w - hi.w));
    ((float4*)g_whh_hi)[i] = hi;
    ((float4*)g_whh_lo)[i] = lo;
}

__global__ void prep_wout(const float* __restrict__ W) {
    int i = blockIdx.x * blockDim.x + threadIdx.x;   // over VOC*EMBD/4
    if (i >= VOC * EMBD / 4) return;
    float4 w = ((const float4*)W)[i];
    ((float4*)g_wout_r)[i] = make_float4(tfr(w.x), tfr(w.y), tfr(w.z), tfr(w.w));
}

// ---------------- pipelined TF32 GEMM: C[M,N] = A[M,K] * B[N,K]^T (+bias) ----
// PRE=true: inputs already tf32-rounded -> no cvt in mainloop.
template <int BM, int BN, int WM, int WN, int NSPLIT, int THREADS, bool PRE>
__global__ void __launch_bounds__(THREADS)
gemm3(const float* __restrict__ A, const float* __restrict__ B,
      float* __restrict__ C,
      const float* __restrict__ bias0, const float* __restrict__ bias1,
      int M, int N, int K) {
    constexpr int BK = 8, LD = 12;
    constexpr int WROWS = BM / WM, WCOLS = BN / WN;
    constexpr int MT = WROWS / 16, NT = WCOLS / 8;
    static_assert(WM * WN == THREADS / 32, "warp grid");

    __shared__ __align__(16) float As[2 * BM * LD];
    __shared__ __align__(16) float Bs[2 * BN * LD];

    const int tid = threadIdx.x, lane = tid & 31, w = tid >> 5;
    const int wm = w / WN, wn = w % WN;
    const int r = lane >> 2, cq = lane & 3;
    const int rowA0 = blockIdx.y * BM, rowB0 = blockIdx.x * BN;

    const uint32_t sA = (uint32_t)__cvta_generic_to_shared(As);
    const uint32_t sB = (uint32_t)__cvta_generic_to_shared(Bs);

    float acc[MT][NT][4] = {};

    auto stage = [&](int kt, int s) {
        for (int i = tid; i < BM * 2; i += THREADS) {
            int row = i >> 1, kq = i & 1;
            const float* src = A + (size_t)(rowA0 + row) * 512 + kt * BK + kq * 4;
            uint32_t dst = sA + (uint32_t)((s * BM + row) * LD + kq * 4) * 4;
            asm volatile("cp.async.cg.shared.global [%0], [%1], 16;\n"
                         :: "r"(dst), "l"(src));
        }
        for (int i = tid; i < BN * 2; i += THREADS) {
            int row = i >> 1, kq = i & 1;
            const float* src = B + (size_t)(rowB0 + row) * 512 + kt * BK + kq * 4;
            uint32_t dst = sB + (uint32_t)((s * BN + row) * LD + kq * 4) * 4;
            asm volatile("cp.async.cg.shared.global [%0], [%1], 16;\n"
                         :: "r"(dst), "l"(src));
        }
        asm volatile("cp.async.commit_group;\n");
    };

    auto frag = [](float x) -> unsigned {
        if constexpr (PRE) return __float_as_uint(x);
        else return f2tf(x);
    };

    const int KT = K / BK;
    stage(0, 0);
    for (int kt = 0; kt < KT; kt++) {
        const int s = kt & 1;
        if (kt + 1 < KT) {
            stage(kt + 1, s ^ 1);
            asm volatile("cp.async.wait_group 1;\n");
        } else {
            asm volatile("cp.async.wait_group 0;\n");
        }
        __syncthreads();

        const float* At = As + s * BM * LD;
        const float* Bt = Bs + s * BN * LD;

        unsigned ah[MT][4], al[MT][4];
#pragma unroll
        for (int mi = 0; mi < MT; mi++) {
            int m0 = wm * WROWS + mi * 16;
            float x0 = At[(m0 + r) * LD + cq];
            float x1 = At[(m0 + r + 8) * LD + cq];
            float x2 = At[(m0 + r) * LD + cq + 4];
            float x3 = At[(m0 + r + 8) * LD + cq + 4];
            ah[mi][0] = frag(x0); ah[mi][1] = frag(x1);
            ah[mi][2] = frag(x2); ah[mi][3] = frag(x3);
            if constexpr (NSPLIT == 2) {
                al[mi][0] = f2tf(x0 - __uint_as_float(ah[mi][0]));
                al[mi][1] = f2tf(x1 - __uint_as_float(ah[mi][1]));
                al[mi][2] = f2tf(x2 - __uint_as_float(ah[mi][2]));
                al[mi][3] = f2tf(x3 - __uint_as_float(ah[mi][3]));
            }
        }
#pragma unroll
        for (int ni = 0; ni < NT; ni++) {
            int n0 = wn * WCOLS + ni * 8;
            float y0 = Bt[(n0 + r) * LD + cq];
            float y1 = Bt[(n0 + r) * LD + cq + 4];
            unsigned bh[2] = {frag(y0), frag(y1)};
            unsigned bl[2];
            if constexpr (NSPLIT == 2) {
                bl[0] = f2tf(y0 - __uint_as_float(bh[0]));
                bl[1] = f2tf(y1 - __uint_as_float(bh[1]));
            }
#pragma unroll
            for (int mi = 0; mi < MT; mi++) {
                mma8(acc[mi][ni], ah[mi], bh);
                if constexpr (NSPLIT == 2) {
                    mma8(acc[mi][ni], ah[mi], bl);
                    mma8(acc[mi][ni], al[mi], bh);
                }
            }
        }
        __syncthreads();
    }

#pragma unroll
    for (int mi = 0; mi < MT; mi++) {
        const int row0 = rowA0 + wm * WROWS + mi * 16 + r;
#pragma unroll
        for (int ni = 0; ni < NT; ni++) {
            const int col = rowB0 + wn * WCOLS + ni * 8 + 2 * cq;
            float b0 = 0.f, b1 = 0.f;
            if (bias0) { b0 += bias0[col]; b1 += bias0[col + 1]; }
            if (bias1) { b0 += bias1[col]; b1 += bias1[col + 1]; }
            float2 o0, o1;
            o0.x = acc[mi][ni][0] + b0;
            o0.y = acc[mi][ni][1] + b1;
            o1.x = acc[mi][ni][2] + b0;
            o1.y = acc[mi][ni][3] + b1;
            *(float2*)(C + (size_t)row0 * N + col) = o0;
            *(float2*)(C + (size_t)(row0 + 8) * N + col) = o1;
        }
    }
}

// ---------------- persistent recurrence: all 19 steps in one kernel ----------
// CTA c owns e in [4c, 4c+4) -> 16 gate columns. 8 warps = 4 m-tiles x 2 n-tiles,
// each warp full K=512 (no reduction). Operands pre-split tf32 hi/lo in gmem ->
// mainloop is pure cp.async + LDS + MMA (zero cvt). Grid-wide gmem barrier
// between steps (128 CTAs <= 148 SMs: all co-resident, deadlock-free).
__global__ void __launch_bounds__(256)
recur_kernel() {
    constexpr int LD = 36;                       // BK=32 row stride (bank-clean, 16B-aligned)
    __shared__ __align__(16) float Ahl[2 * 2 * 64 * LD];   // [buf][plane][64][LD] 36864 B
    __shared__ __align__(16) float Bhl[2 * 2 * 16 * LD];   //  9216 B
    float* G = Ahl;                              // alias after mainloop: gates [64][16]

    const int c = blockIdx.x;
    const int tid = threadIdx.x, lane = tid & 31, w = tid >> 5;
    const int mi = w >> 1, ni = w & 1;
    const int r = lane >> 2, cq = lane & 3;
    const int m0 = mi * 16, n0 = ni * 8;

    const uint32_t sA = (uint32_t)__cvta_generic_to_shared(Ahl);
    const uint32_t sB = (uint32_t)__cvta_generic_to_shared(Bhl);

    for (int s = 0; s < NSTEP; s++) {
        auto stage = [&](int kt, int buf) {
            // A: h hi/lo planes, 64 rows x 32 K, 8 x 16B chunks per row per plane
            for (int i = tid; i < 1024; i += 256) {
                int plane = i >> 9, rem = i & 511, row = rem >> 3, ch = rem & 7;
                const float* base = plane ? g_h_lo : g_h_hi;
                const float* src = base + row * 512 + kt * 32 + ch * 4;
                uint32_t dst = sA + (uint32_t)(((buf * 2 + plane) * 64 + row) * LD + ch * 4) * 4;
                asm volatile("cp.async.cg.shared.global [%0], [%1], 16;\n"
                             :: "r"(dst), "l"(src));
            }
            // B: W_hh hi/lo planes, 16 gate-rows x 32 K
            for (int i = tid; i < 256; i += 256) {
                int plane = i >> 7, rem = i & 127, row = rem >> 3, ch = rem & 7;
                int grow = (row >> 2) * 512 + c * ETILE + (row & 3);
                const float* base = plane ? g_whh_lo : g_whh_hi;
                const float* src = base + (size_t)grow * 512 + kt * 32 + ch * 4;
                uint32_t dst = sB + (uint32_t)(((buf * 2 + plane) * 16 + row) * LD + ch * 4) * 4;
                asm volatile("cp.async.cg.shared.global [%0], [%1], 16;\n"
                             :: "r"(dst), "l"(src));
            }
            asm volatile("cp.async.commit_group;\n");
        };

        float acc[4] = {};
        stage(0, 0);
        for (int kt = 0; kt < 16; kt++) {        // K=512 / BK=32
            const int buf = kt & 1;
            if (kt + 1 < 16) {
                stage(kt + 1, buf ^ 1);
                asm volatile("cp.async.wait_group 1;\n");
            } else {
                asm volatile("cp.async.wait_group 0;\n");
            }
            __syncthreads();

            const float* Ah = Ahl + (buf * 2 + 0) * 64 * LD;
            const float* Al = Ahl + (buf * 2 + 1) * 64 * LD;
            const float* Bh = Bhl + (buf * 2 + 0) * 16 * LD;
            const float* Bl = Bhl + (buf * 2 + 1) * 16 * LD;
#pragma unroll
            for (int kk = 0; kk < 32; kk += 8) {
                unsigned ah[4] = {__float_as_uint(Ah[(m0 + r) * LD + kk + cq]),
                                  __float_as_uint(Ah[(m0 + r + 8) * LD + kk + cq]),
                                  __float_as_uint(Ah[(m0 + r) * LD + kk + cq + 4]),
                                  __float_as_uint(Ah[(m0 + r + 8) * LD + kk + cq + 4])};
                unsigned al[4] = {__float_as_uint(Al[(m0 + r) * LD + kk + cq]),
                                  __float_as_uint(Al[(m0 + r + 8) * LD + kk + cq]),
                                  __float_as_uint(Al[(m0 + r) * LD + kk + cq + 4]),
                                  __float_as_uint(Al[(m0 + r + 8) * LD + kk + cq + 4])};
                unsigned bh[2] = {__float_as_uint(Bh[(n0 + r) * LD + kk + cq]),
                                  __float_as_uint(Bh[(n0 + r) * LD + kk + cq + 4])};
                unsigned bl[2] = {__float_as_uint(Bl[(n0 + r) * LD + kk + cq]),
                                  __float_as_uint(Bl[(n0 + r) * LD + kk + cq + 4])};
                mma8(acc, ah, bh);
                mma8(acc, ah, bl);
                mma8(acc, al, bh);
            }
            __syncthreads();
        }

        // gates tile -> smem (aliases A buffer; mainloop done, protected by sync above)
        G[(m0 + r) * 16 + n0 + 2 * cq]     = acc[0];
        G[(m0 + r) * 16 + n0 + 2 * cq + 1] = acc[1];
        G[(m0 + r + 8) * 16 + n0 + 2 * cq]     = acc[2];
        G[(m0 + r + 8) * 16 + n0 + 2 * cq + 1] = acc[3];
        __syncthreads();

        // cell: thread -> (batch b, e-offset j)
        {
            int b = tid >> 2, j = tid & 3;
            int e = c * ETILE + j;
            const float* xp = g_xpre + ((size_t)s * BB + b) * GDIM;
            float gi = xp[e]        + G[b * 16 + j];
            float gf = xp[512 + e]  + G[b * 16 + 4 + j];
            float gg = xp[1024 + e] + G[b * 16 + 8 + j];
            float go = xp[1536 + e] + G[b * 16 + 12 + j];
            float cold = g_c[b * EMBD + e];
            float cn = fsig(gf) * cold + fsig(gi) * ftanh(gg);
            float hn = fsig(go) * ftanh(cn);
            g_c[b * EMBD + e] = cn;
            float hi = __uint_as_float(f2tf(hn));
            g_h_hi[b * EMBD + e] = hi;
            g_h_lo[b * EMBD + e] = __uint_as_float(f2tf(hn - hi));
            g_seq[((size_t)b * TT + (s + 1)) * EMBD + e] = hi;   // tf32-rounded for proj
        }

        // grid-wide barrier before next step
        if (s + 1 < NSTEP) {
            __threadfence();
            __syncthreads();
            if (tid == 0) {
                atomicAdd(&g_bar, 1u);
                unsigned target = (unsigned)(s + 1) * NCTA;
                while (*(volatile unsigned*)&g_bar < target) __nanosleep(64);
                __threadfence();
            }
            __syncthreads();
        }
    }
}

// ---------------- launch ----------------
extern "C" void kernel_launch(void* const* d_in, const int* in_sizes, int n_in,
                              void* d_out, int out_size) {
    const float* features = (const float*)d_in[0];
    const int*   captions = (const int*)d_in[1];
    const float* W_emb    = (const float*)d_in[2];
    const float* W_out    = (const float*)d_in[3];
    const float* b_out    = (const float*)d_in[4];
    const float* W_ih     = (const float*)d_in[5];
    const float* W_hh     = (const float*)d_in[6];
    const float* b_ih     = (const float*)d_in[7];
    const float* b_hh     = (const float*)d_in[8];
    float* out = (float*)d_out;
    (void)in_sizes; (void)n_in; (void)out_size;

    float *p_emb, *p_xpre, *p_seq, *p_wout;
    cudaGetSymbolAddress((void**)&p_emb,  g_embsteps);
    cudaGetSymbolAddress((void**)&p_xpre, g_xpre);
    cudaGetSymbolAddress((void**)&p_seq,  g_seq);
    cudaGetSymbolAddress((void**)&p_wout, g_wout_r);

    // 1) gather embeddings, init h0/c0, reset barrier; prep weight planes
    init_kernel<<<(BB * TT * (EMBD / 4) + 255) / 256, 256>>>(features, captions, W_emb);
    prep_whh<<<(GDIM * EMBD / 4 + 255) / 256, 256>>>(W_hh);
    prep_wout<<<(VOC * EMBD / 4 + 255) / 256, 256>>>(W_out);

    // 2) xpre = emb @ W_ih^T + b_ih + b_hh   (3xTF32; M=1216=19*64 exact)
    gemm3<64, 128, 2, 4, 2, 256, false><<<dim3(GDIM / 128, NSTEP * BB / 64, 1), 256>>>(
        p_emb, W_ih, p_xpre, b_ih, b_hh, NSTEP * BB, GDIM, EMBD);

    // 3) entire recurrence in ONE persistent kernel (19 steps, grid barrier)
    recur_kernel<<<NCTA, 256>>>();

    // 4) logits = seq @ W_out^T + b_out   (pre-rounded operands, cvt-free mainloop)
    gemm3<128, 256, 4, 4, 1, 512, true><<<dim3(VOC / 256, BB * TT / 128, 1), 512>>>(
        p_seq, p_wout, out, b_out, nullptr, BB * TT, VOC, EMBD);
}